// round 15
// baseline (speedup 1.0000x reference)
#include <cuda_runtime.h>
#include <math.h>
#include <stdint.h>

#define NSLOT 9
#define DD    64
#define TILE  128   // points per block (4 warps x 32 points)
#define BLK   128

typedef unsigned long long u64;

// ---------------- packed f32x2 helpers ----------------
__device__ __forceinline__ u64 ffma2(u64 a, u64 b, u64 c) {
    u64 d;
    asm("fma.rn.f32x2 %0, %1, %2, %3;" : "=l"(d) : "l"(a), "l"(b), "l"(c));
    return d;
}
__device__ __forceinline__ u64 pack2(float x, float y) {
    u64 r; asm("mov.b64 %0, {%1, %2};" : "=l"(r) : "f"(x), "f"(y)); return r;
}
__device__ __forceinline__ u64 pack2dup(float x) {
    u64 r; asm("mov.b64 %0, {%1, %1};" : "=l"(r) : "f"(x)); return r;
}
__device__ __forceinline__ void unpack2(u64 v, float &x, float &y) {
    asm("mov.b64 {%0, %1}, %2;" : "=f"(x), "=f"(y) : "l"(v));
}
__device__ __forceinline__ void lds128(u64 &lo, u64 &hi, const void* p) {
    unsigned s = (unsigned)__cvta_generic_to_shared(p);
    asm("ld.shared.v2.b64 {%0, %1}, [%2];" : "=l"(lo), "=l"(hi) : "r"(s));
}

// ---------------- precomputed per-batch tables ----------------
__device__ float g_ck[2][NSLOT][DD];   // SCALE * Wq^T k_j
__device__ float g_c0[2][NSLOT];       // SCALE * Wq_b . k_j
__device__ float g_M [2][NSLOT][DD];   // slots_full[j] @ out_w^T
__device__ float g_sscale;             // exp(density_scale)

// grid = (NSLOT, B), block = 256 : 4-way split of the 64-term reductions
__global__ void __launch_bounds__(256)
precompute_kernel(const float* __restrict__ slots,
                  const float* __restrict__ empty_slot,
                  const float* __restrict__ Wq_w,
                  const float* __restrict__ Wq_b,
                  const float* __restrict__ Wk_w,
                  const float* __restrict__ Wk_b,
                  const float* __restrict__ out_w,
                  const float* __restrict__ density_scale)
{
    const int j    = blockIdx.x;
    const int b    = blockIdx.y;
    const int tid  = threadIdx.x;
    const int d    = tid & 63;
    const int part = tid >> 6;            // 0..3
    __shared__ float sf[DD];
    __shared__ float kv[DD];
    __shared__ float pK[4][DD];
    __shared__ float pM[4][DD];

    if (tid < DD)
        sf[tid] = (j == 0) ? empty_slot[tid]
                           : slots[((size_t)b * 8 + (j - 1)) * DD + tid];
    __syncthreads();

    {
        const float4* wk4 = (const float4*)(Wk_w  + (size_t)d * DD) + part * 4;
        const float4* ow4 = (const float4*)(out_w + (size_t)d * DD) + part * 4;
        const float4* sf4 = (const float4*)sf + part * 4;
        float aK = 0.f, aM = 0.f;
        #pragma unroll
        for (int c = 0; c < 4; ++c) {
            float4 s4 = sf4[c], k4 = wk4[c], o4 = ow4[c];
            aK = fmaf(s4.x, k4.x, aK); aK = fmaf(s4.y, k4.y, aK);
            aK = fmaf(s4.z, k4.z, aK); aK = fmaf(s4.w, k4.w, aK);
            aM = fmaf(s4.x, o4.x, aM); aM = fmaf(s4.y, o4.y, aM);
            aM = fmaf(s4.z, o4.z, aM); aM = fmaf(s4.w, o4.w, aM);
        }
        pK[part][d] = aK;
        pM[part][d] = aM;
    }
    __syncthreads();
    if (part == 0) {
        kv[d]        = Wk_b[d] + pK[0][d] + pK[1][d] + pK[2][d] + pK[3][d];
        g_M[b][j][d] = pM[0][d] + pM[1][d] + pM[2][d] + pM[3][d];
    }
    __syncthreads();

    {
        float a = 0.f;
        const int dd0 = part * 16;
        #pragma unroll
        for (int k = 0; k < 16; ++k)
            a = fmaf(Wq_w[(size_t)(dd0 + k) * DD + d], kv[dd0 + k], a);
        pK[part][d] = a;
    }
    __syncthreads();
    if (part == 0)
        g_ck[b][j][d] = 0.125f * (pK[0][d] + pK[1][d] + pK[2][d] + pK[3][d]);
    if (tid == 64) {
        float a = 0.f;
        #pragma unroll 8
        for (int dd = 0; dd < DD; ++dd)
            a = fmaf(Wq_b[dd], kv[dd], a);
        g_c0[b][j] = a * 0.125f;
    }
    if (b == 0 && j == 0 && tid == 0) g_sscale = expf(density_scale[0]);
}

// ---------------- main kernel: warp-independent subtiles, no per-tile CTA barriers ----------------
__global__ void __launch_bounds__(BLK)
points_kernel(const float* __restrict__ x,
              const float* __restrict__ coor,
              float* __restrict__ xo,
              float* __restrict__ wout,
              float* __restrict__ sig,
              const float* __restrict__ out_b,
              int Npts)
{
    __shared__ float4 xs4[4][512];             // 8 KB per warp slab (aliased as wbuf)
    __shared__ float4 sCK4[NSLOT * 16];        // 2.25 KB
    __shared__ float  sC0[NSLOT];
    __shared__ float  sScale;

    const int b    = blockIdx.y;
    const int t    = threadIdx.x;
    const int wid  = t >> 5;
    const int lane = t & 31;

    // ---- CTA prologue: shared tables (one barrier total) ----
    {
        const float4* gck = (const float4*)&g_ck[b][0][0];
        for (int i = t; i < NSLOT * 16; i += BLK) sCK4[i] = gck[i];
        if (t < NSLOT) sC0[t] = g_c0[b][t];
        if (t == 0)    sScale = g_sscale;
    }
    __syncthreads();

    // ---- warp-local subtile: 32 points ----
    const int wbase0 = blockIdx.x * TILE + wid * 32;      // warp's first point
    const int wvalid = min(32, Npts - wbase0);
    if (wvalid <= 0) return;
    const size_t base = (size_t)b * Npts + wbase0;

    // coor prefetch (32 lanes -> 1 point each)
    float cx = 0.f, cy = 0.f, cz = 0.f;
    if (lane < wvalid) {
        const float* cp = coor + (base + lane) * 3;
        cx = cp[0]; cy = cp[1]; cz = cp[2];
    }

    float4* slab = xs4[wid];
    float*  wbuf = (float*)slab;     // alias: stride-12 [pt][0..8,pad3] (384 floats)

    // ---- phase A: stage 32 rows (coalesced LDG, swizzled STS), warp-private ----
    {
        const float4* gx = (const float4*)(x + base * DD);
        #pragma unroll
        for (int kk = 0; kk < 16; ++kk) {
            int i   = kk * 32 + lane;              // 0..511
            int row = i >> 4, ch = i & 15;
            if (row < wvalid)
                slab[(row << 4) | (ch ^ (row & 7))] = gx[i];
        }
    }
    __syncwarp();

    // ---- phase B: logits + softmax, 1 point/lane ----
    float wv[NSLOT];
    float sg = 0.f;
    const bool active = (lane < wvalid);
    if (active) {
        u64 acc[NSLOT];
        #pragma unroll
        for (int j = 0; j < NSLOT; ++j) acc[j] = 0ull;

        const float4* xr = &slab[lane << 4];
        const int sw = lane & 7;
        #pragma unroll
        for (int c = 0; c < 16; ++c) {
            u64 xlo, xhi;
            lds128(xlo, xhi, &xr[c ^ sw]);
            #pragma unroll
            for (int j = 0; j < NSLOT; ++j) {
                u64 clo, chi;
                lds128(clo, chi, &sCK4[j * 16 + c]);
                acc[j] = ffma2(xlo, clo, acc[j]);
                acc[j] = ffma2(xhi, chi, acc[j]);
            }
        }
        float lg[NSLOT];
        #pragma unroll
        for (int j = 0; j < NSLOT; ++j) {
            float lo, hi; unpack2(acc[j], lo, hi);
            lg[j] = lo + hi + sC0[j];
        }

        bool oob = (fabsf(cx) > 1.0f) || (fabsf(cy) > 1.0f) || (fabsf(cz) > 1.0f);
        const int kmax = oob ? 2 : NSLOT;

        float m = fmaxf(lg[0], lg[1]);
        if (!oob) {
            #pragma unroll
            for (int j = 2; j < NSLOT; ++j) m = fmaxf(m, lg[j]);
        }
        float sum = 0.f;
        #pragma unroll
        for (int j = 0; j < NSLOT; ++j) {
            float e = (j < kmax) ? __expf(lg[j] - m) : 0.f;
            wv[j] = e; sum += e;
        }
        const float inv = __frcp_rn(sum);
        #pragma unroll
        for (int j = 1; j < NSLOT; ++j)
            sg = fmaf(fmaxf(lg[j], 0.f), wv[j], sg);
        sg *= inv * sScale;
        #pragma unroll
        for (int j = 0; j < NSLOT; ++j) wv[j] *= inv;
    }
    __syncwarp();        // all slab reads done -> alias safe

    if (active) {
        sig[base + lane] = sg;
        float* wp = &wbuf[lane * 12];
        ((float4*)wp)[0] = make_float4(wv[0], wv[1], wv[2], wv[3]);
        ((float4*)wp)[1] = make_float4(wv[4], wv[5], wv[6], wv[7]);
        ((float4*)wp)[2] = make_float4(wv[8], 0.f, 0.f, 0.f);
    }
    __syncwarp();

    // ---- phase C: xo = w @ M + out_b ; emit w.  lane = (group g, chunk ch) ----
    {
        const int g  = lane >> 4;        // 0..1 : group of 16 points
        const int ch = lane & 15;        // f4 chunk of the 64-float row
        u64 Mlo[NSLOT], Mhi[NSLOT];
        #pragma unroll
        for (int j = 0; j < NSLOT; ++j) {
            float4 mv = ((const float4*)&g_M[b][j][0])[ch];
            Mlo[j] = pack2(mv.x, mv.y);
            Mhi[j] = pack2(mv.z, mv.w);
        }
        float4 obv = ((const float4*)out_b)[ch];
        const u64 oblo = pack2(obv.x, obv.y), obhi = pack2(obv.z, obv.w);

        float4* go = (float4*)(xo + base * DD);
        float*  gw = wout + base * (size_t)NSLOT;
        #pragma unroll 4
        for (int i = 0; i < 16; ++i) {
            int pt = g * 16 + i;
            if (pt < wvalid) {
                const float* wp = &wbuf[pt * 12];
                u64 w01, w23, w45, w67;
                lds128(w01, w23, wp);
                lds128(w45, w67, wp + 4);
                float w0,w1,w2,w3,w4,w5,w6,w7;
                unpack2(w01, w0, w1); unpack2(w23, w2, w3);
                unpack2(w45, w4, w5); unpack2(w67, w6, w7);
                float w8 = wp[8];
                float wreg[NSLOT] = {w0,w1,w2,w3,w4,w5,w6,w7,w8};

                u64 olo = oblo, ohi = obhi;
                #pragma unroll
                for (int j = 0; j < NSLOT; ++j) {
                    u64 wj = pack2dup(wreg[j]);
                    olo = ffma2(wj, Mlo[j], olo);
                    ohi = ffma2(wj, Mhi[j], ohi);
                }
                float4 o;
                unpack2(olo, o.x, o.y);
                unpack2(ohi, o.z, o.w);
                go[pt * 16 + ch] = o;            // lanes 0-15 one contiguous row

                if (ch < NSLOT)
                    gw[(size_t)pt * NSLOT + ch] = wreg[ch];
            }
        }
    }
}

extern "C" void kernel_launch(void* const* d_in, const int* in_sizes, int n_in,
                              void* d_out, int out_size)
{
    const float* point_feats   = (const float*)d_in[0];
    // d_in[1] = points_emb (unused by the scored block)
    const float* slots         = (const float*)d_in[2];
    const float* coor          = (const float*)d_in[3];
    const float* empty_slot    = (const float*)d_in[4];
    const float* Wq_w          = (const float*)d_in[5];
    const float* Wq_b          = (const float*)d_in[6];
    const float* Wk_w          = (const float*)d_in[7];
    const float* Wk_b          = (const float*)d_in[8];
    const float* out_w         = (const float*)d_in[9];
    const float* out_b         = (const float*)d_in[10];
    const float* density_scale = (const float*)d_in[11];

    const int B    = in_sizes[2] / (8 * 64);      // slots: [B, 8, 64]
    const int Npts = in_sizes[0] / (B * 64);      // point_feats: [B, N, 64]

    float* xo   = (float*)d_out;                                  // [B, N, 64]
    float* wout = xo + (size_t)B * Npts * 64;                     // [B, N, 9]
    float* sg   = wout + (size_t)B * Npts * 9;                    // [B, N]

    dim3 pgrid(NSLOT, B);
    precompute_kernel<<<pgrid, 256>>>(slots, empty_slot, Wq_w, Wq_b,
                                      Wk_w, Wk_b, out_w, density_scale);

    dim3 grid((Npts + TILE - 1) / TILE, B);
    points_kernel<<<grid, BLK>>>(point_feats, coor, xo, wout, sg, out_b, Npts);
}

// round 16
// speedup vs baseline: 1.0468x; 1.0468x over previous
#include <cuda_runtime.h>
#include <math.h>
#include <stdint.h>

#define NSLOT 9
#define DD    64
#define TILE  128   // points per block
#define BLK   128   // threads per block

typedef unsigned long long u64;

// ---------------- packed f32x2 helpers ----------------
__device__ __forceinline__ u64 ffma2(u64 a, u64 b, u64 c) {
    u64 d;
    asm("fma.rn.f32x2 %0, %1, %2, %3;" : "=l"(d) : "l"(a), "l"(b), "l"(c));
    return d;
}
__device__ __forceinline__ u64 pack2(float x, float y) {
    u64 r; asm("mov.b64 %0, {%1, %2};" : "=l"(r) : "f"(x), "f"(y)); return r;
}
__device__ __forceinline__ u64 pack2dup(float x) {
    u64 r; asm("mov.b64 %0, {%1, %1};" : "=l"(r) : "f"(x)); return r;
}
__device__ __forceinline__ void unpack2(u64 v, float &x, float &y) {
    asm("mov.b64 {%0, %1}, %2;" : "=f"(x), "=f"(y) : "l"(v));
}
__device__ __forceinline__ void lds128(u64 &lo, u64 &hi, const void* p) {
    unsigned s = (unsigned)__cvta_generic_to_shared(p);
    asm("ld.shared.v2.b64 {%0, %1}, [%2];" : "=l"(lo), "=l"(hi) : "r"(s));
}
__device__ __forceinline__ void griddep_wait() {
    asm volatile("griddepcontrol.wait;" ::: "memory");
}

// ---------------- precomputed per-batch tables ----------------
__device__ float g_ck[2][NSLOT][DD];   // SCALE * Wq^T k_j
__device__ float g_c0[2][NSLOT];       // SCALE * Wq_b . k_j
__device__ float g_M [2][NSLOT][DD];   // slots_full[j] @ out_w^T
__device__ float g_sscale;             // exp(density_scale)

// grid = (NSLOT, B), block = 256 : 4-way split of the 64-term reductions
__global__ void __launch_bounds__(256)
precompute_kernel(const float* __restrict__ slots,
                  const float* __restrict__ empty_slot,
                  const float* __restrict__ Wq_w,
                  const float* __restrict__ Wq_b,
                  const float* __restrict__ Wk_w,
                  const float* __restrict__ Wk_b,
                  const float* __restrict__ out_w,
                  const float* __restrict__ density_scale)
{
    const int j    = blockIdx.x;
    const int b    = blockIdx.y;
    const int tid  = threadIdx.x;
    const int d    = tid & 63;
    const int part = tid >> 6;            // 0..3
    __shared__ float sf[DD];
    __shared__ float kv[DD];
    __shared__ float pK[4][DD];
    __shared__ float pM[4][DD];

    if (tid < DD)
        sf[tid] = (j == 0) ? empty_slot[tid]
                           : slots[((size_t)b * 8 + (j - 1)) * DD + tid];
    __syncthreads();

    {
        const float4* wk4 = (const float4*)(Wk_w  + (size_t)d * DD) + part * 4;
        const float4* ow4 = (const float4*)(out_w + (size_t)d * DD) + part * 4;
        const float4* sf4 = (const float4*)sf + part * 4;
        float aK = 0.f, aM = 0.f;
        #pragma unroll
        for (int c = 0; c < 4; ++c) {
            float4 s4 = sf4[c], k4 = wk4[c], o4 = ow4[c];
            aK = fmaf(s4.x, k4.x, aK); aK = fmaf(s4.y, k4.y, aK);
            aK = fmaf(s4.z, k4.z, aK); aK = fmaf(s4.w, k4.w, aK);
            aM = fmaf(s4.x, o4.x, aM); aM = fmaf(s4.y, o4.y, aM);
            aM = fmaf(s4.z, o4.z, aM); aM = fmaf(s4.w, o4.w, aM);
        }
        pK[part][d] = aK;
        pM[part][d] = aM;
    }
    __syncthreads();
    if (part == 0) {
        kv[d]        = Wk_b[d] + pK[0][d] + pK[1][d] + pK[2][d] + pK[3][d];
        g_M[b][j][d] = pM[0][d] + pM[1][d] + pM[2][d] + pM[3][d];
    }
    __syncthreads();

    {
        float a = 0.f;
        const int dd0 = part * 16;
        #pragma unroll
        for (int k = 0; k < 16; ++k)
            a = fmaf(Wq_w[(size_t)(dd0 + k) * DD + d], kv[dd0 + k], a);
        pK[part][d] = a;
    }
    __syncthreads();
    if (part == 0)
        g_ck[b][j][d] = 0.125f * (pK[0][d] + pK[1][d] + pK[2][d] + pK[3][d]);
    if (tid == 64) {
        float a = 0.f;
        #pragma unroll 8
        for (int dd = 0; dd < DD; ++dd)
            a = fmaf(Wq_b[dd], kv[dd], a);
        g_c0[b][j] = a * 0.125f;
    }
    if (b == 0 && j == 0 && tid == 0) g_sscale = expf(density_scale[0]);
}

// ---------------- main per-point kernel (R11 champion + PDL + cache hints) ----------------
__global__ void __launch_bounds__(BLK, 5)
points_kernel(const float* __restrict__ x,
              const float* __restrict__ coor,
              float* __restrict__ xo,
              float* __restrict__ wout,
              float* __restrict__ sig,
              const float* __restrict__ out_b,
              int Npts)
{
    __shared__ float4 xs4[TILE * 16];          // 32 KB, xor-swizzled rows
    __shared__ float  wbuf[TILE * 12];         // 6 KB, stride-12 padded
    __shared__ float4 sCK4[NSLOT * 16];        // 2.25 KB
    __shared__ float  sC0[NSLOT];
    __shared__ float  sScale;

    const int b     = blockIdx.y;
    const int t     = threadIdx.x;
    const int tile0 = blockIdx.x * TILE;
    const int valid = min(TILE, Npts - tile0);
    const size_t base = (size_t)b * Npts + tile0;

    // ---- phase A FIRST (independent of precompute): stage x tile ----
    {
        const float4* gx = (const float4*)(x + base * DD);
        #pragma unroll
        for (int kk = 0; kk < 16; ++kk) {
            int i   = kk * BLK + t;
            int row = i >> 4, ch = i & 15;
            if (row < valid)
                xs4[(row << 4) | (ch ^ (row & 7))] = __ldcs(gx + i);
        }
    }

    // coor prefetch (also precompute-independent)
    float cx = 0.f, cy = 0.f, cz = 0.f;
    if (t < valid) {
        const float* cp = coor + (base + t) * 3;
        cx = __ldcs(cp);  cy = __ldcs(cp + 1);  cz = __ldcs(cp + 2);
    }

    // ---- wait for precompute tables, then load them ----
    griddep_wait();
    {
        const float4* gck = (const float4*)&g_ck[b][0][0];
        for (int i = t; i < NSLOT * 16; i += BLK) sCK4[i] = gck[i];
        if (t < NSLOT) sC0[t] = g_c0[b][t];
        if (t == 0)    sScale = g_sscale;
    }
    __syncthreads();

    // ---- phase B: logits + softmax, 1 point/thread ----
    if (t < valid) {
        u64 acc[NSLOT];
        #pragma unroll
        for (int j = 0; j < NSLOT; ++j) acc[j] = 0ull;

        const float4* xr = &xs4[t << 4];
        const int sw = t & 7;
        #pragma unroll
        for (int c = 0; c < 16; ++c) {
            u64 xlo, xhi;
            lds128(xlo, xhi, &xr[c ^ sw]);
            #pragma unroll
            for (int j = 0; j < NSLOT; ++j) {
                u64 clo, chi;
                lds128(clo, chi, &sCK4[j * 16 + c]);
                acc[j] = ffma2(xlo, clo, acc[j]);
                acc[j] = ffma2(xhi, chi, acc[j]);
            }
        }
        float lg[NSLOT];
        #pragma unroll
        for (int j = 0; j < NSLOT; ++j) {
            float lo, hi; unpack2(acc[j], lo, hi);
            lg[j] = lo + hi + sC0[j];
        }

        bool oob = (fabsf(cx) > 1.0f) || (fabsf(cy) > 1.0f) || (fabsf(cz) > 1.0f);
        const int kmax = oob ? 2 : NSLOT;

        float m = fmaxf(lg[0], lg[1]);
        if (!oob) {
            #pragma unroll
            for (int j = 2; j < NSLOT; ++j) m = fmaxf(m, lg[j]);
        }
        float w[NSLOT], sum = 0.f;
        #pragma unroll
        for (int j = 0; j < NSLOT; ++j) {
            float e = (j < kmax) ? __expf(lg[j] - m) : 0.f;
            w[j] = e; sum += e;
        }
        const float inv = __frcp_rn(sum);

        float sg = 0.f;
        #pragma unroll
        for (int j = 1; j < NSLOT; ++j)
            sg = fmaf(fmaxf(lg[j], 0.f), w[j], sg);
        __stcs(sig + base + t, sg * inv * sScale);

        float* wp = &wbuf[t * 12];
        ((float4*)wp)[0] = make_float4(w[0]*inv, w[1]*inv, w[2]*inv, w[3]*inv);
        ((float4*)wp)[1] = make_float4(w[4]*inv, w[5]*inv, w[6]*inv, w[7]*inv);
        ((float4*)wp)[2] = make_float4(w[8]*inv, 0.f, 0.f, 0.f);
    }
    __syncthreads();

    // ---- phase C: xo = w @ M + out_b; also emit w to global ----
    {
        const int g  = t >> 4;     // 0..7 : group of 16 points
        const int ch = t & 15;     // f4 chunk of the 64-float row
        u64 Mlo[NSLOT], Mhi[NSLOT];
        #pragma unroll
        for (int j = 0; j < NSLOT; ++j) {
            float4 mv = ((const float4*)&g_M[b][j][0])[ch];
            Mlo[j] = pack2(mv.x, mv.y);
            Mhi[j] = pack2(mv.z, mv.w);
        }
        float4 obv = ((const float4*)out_b)[ch];
        const u64 oblo = pack2(obv.x, obv.y), obhi = pack2(obv.z, obv.w);

        float4* go = (float4*)(xo + base * DD);
        float*  gw = wout + base * (size_t)NSLOT;
        #pragma unroll 4
        for (int i = 0; i < 16; ++i) {
            int pt = g * 16 + i;
            if (pt < valid) {
                const float* wp = &wbuf[pt * 12];
                u64 w01, w23, w45, w67;
                lds128(w01, w23, wp);
                lds128(w45, w67, wp + 4);
                float w0,w1,w2,w3,w4,w5,w6,w7,w8;
                unpack2(w01, w0, w1); unpack2(w23, w2, w3);
                unpack2(w45, w4, w5); unpack2(w67, w6, w7);
                w8 = wp[8];
                float wv[NSLOT] = {w0,w1,w2,w3,w4,w5,w6,w7,w8};

                u64 olo = oblo, ohi = obhi;
                #pragma unroll
                for (int j = 0; j < NSLOT; ++j) {
                    u64 wj = pack2dup(wv[j]);
                    olo = ffma2(wj, Mlo[j], olo);
                    ohi = ffma2(wj, Mhi[j], ohi);
                }
                float4 o;
                unpack2(olo, o.x, o.y);
                unpack2(ohi, o.z, o.w);
                __stcs(go + pt * 16 + ch, o);         // lanes 0-15 one row: coalesced

                if (ch < NSLOT)
                    __stcs(gw + (size_t)pt * NSLOT + ch, wv[ch]);
            }
        }
    }
}

extern "C" void kernel_launch(void* const* d_in, const int* in_sizes, int n_in,
                              void* d_out, int out_size)
{
    const float* point_feats   = (const float*)d_in[0];
    // d_in[1] = points_emb (unused by the scored block)
    const float* slots         = (const float*)d_in[2];
    const float* coor          = (const float*)d_in[3];
    const float* empty_slot    = (const float*)d_in[4];
    const float* Wq_w          = (const float*)d_in[5];
    const float* Wq_b          = (const float*)d_in[6];
    const float* Wk_w          = (const float*)d_in[7];
    const float* Wk_b          = (const float*)d_in[8];
    const float* out_w         = (const float*)d_in[9];
    const float* out_b         = (const float*)d_in[10];
    const float* density_scale = (const float*)d_in[11];

    const int B    = in_sizes[2] / (8 * 64);      // slots: [B, 8, 64]
    int Npts = in_sizes[0] / (B * 64);            // point_feats: [B, N, 64]

    float* xo   = (float*)d_out;                                  // [B, N, 64]
    float* wout = xo + (size_t)B * Npts * 64;                     // [B, N, 9]
    float* sg   = wout + (size_t)B * Npts * 9;                    // [B, N]

    dim3 pgrid(NSLOT, B);
    precompute_kernel<<<pgrid, 256>>>(slots, empty_slot, Wq_w, Wq_b,
                                      Wk_w, Wk_b, out_w, density_scale);

    // points_kernel with programmatic dependent launch: starts overlapped with
    // precompute; griddepcontrol.wait inside orders the table reads.
    dim3 grid((Npts + TILE - 1) / TILE, B);
    cudaLaunchConfig_t cfg = {};
    cfg.gridDim  = grid;
    cfg.blockDim = dim3(BLK, 1, 1);
    cfg.stream   = 0;
    cudaLaunchAttribute attrs[1];
    attrs[0].id = cudaLaunchAttributeProgrammaticStreamSerialization;
    attrs[0].val.programmaticStreamSerializationAllowed = 1;
    cfg.attrs    = attrs;
    cfg.numAttrs = 1;
    cudaLaunchKernelEx(&cfg, points_kernel,
                       point_feats, coor, xo, wout, sg,
                       (const float*)d_in[10], Npts);
}